// round 7
// baseline (speedup 1.0000x reference)
#include <cuda_runtime.h>
#include <cuda_bf16.h>
#include <math.h>

// ---------------------------------------------------------------------------
// Problem constants
// ---------------------------------------------------------------------------
#define BATCH 64
#define NNODE 256
#define CT    3
#define HID   256
#define HEADS 4
#define CCH   64              // HID / HEADS
#define EDGES 8192
#define FIN   (NNODE * CT)    // 768
#define MROWS (BATCH * NNODE) // 16384
#define NEG_SLOPE 0.2f
#define EPS_BN 1e-5f

// ---------------------------------------------------------------------------
// Scratch (static device globals: allocation-free, graph-capture safe)
// ---------------------------------------------------------------------------
__device__ float g_h [MROWS * HID];
__device__ float g_xl[MROWS * HID];
__device__ float g_xr[MROWS * HID];
__device__ float g_hA[MROWS * HID];
__device__ float g_hB[MROWS * HID];
__device__ int   g_row_ptr[NNODE + 1];
__device__ int   g_col_src[EDGES];

__device__ __forceinline__ float gelu_f(float x) {
    return 0.5f * x * (1.0f + erff(x * 0.70710678118654752f));
}

// ---------------------------------------------------------------------------
// Deterministic CSR build over dst (stable: preserves edge order per bucket)
// One block of 256 threads; thread n owns node n.
// ---------------------------------------------------------------------------
__global__ void build_csr_kernel(const int* __restrict__ ei) {
    __shared__ int cnt[NNODE + 1];
    const int n = threadIdx.x;
    const int* __restrict__ src = ei;
    const int* __restrict__ dst = ei + EDGES;

    int c = 0;
    for (int e = 0; e < EDGES; ++e) c += (dst[e] == n);
    cnt[n + 1] = c;
    if (n == 0) cnt[0] = 0;
    __syncthreads();
    if (n == 0) {
        for (int i = 1; i <= NNODE; ++i) cnt[i] += cnt[i - 1];
    }
    __syncthreads();
    g_row_ptr[n] = cnt[n];
    if (n == NNODE - 1) g_row_ptr[NNODE] = cnt[NNODE];

    int pos = cnt[n];
    for (int e = 0; e < EDGES; ++e) {
        if (dst[e] == n) g_col_src[pos++] = src[e];
    }
}

// ---------------------------------------------------------------------------
// Tiled fp32 GEMM: C = epilogue(A[MxK] @ W[KxN] + bias)
// epi == 1 -> BatchNorm (eval) + exact GELU ; epi == 0 -> bias only
// BM=128, BN=64, BK=16, TM=8, TN=4, 256 threads.
// Requires M%128==0, N%64==0, K%16==0 (holds for all shapes here).
// ---------------------------------------------------------------------------
#define GBM 128
#define GBN 64
#define GBK 16
#define GTM 8
#define GTN 4

__global__ __launch_bounds__(256, 2)
void gemm_kernel(const float* __restrict__ A, const float* __restrict__ W,
                 const float* __restrict__ bias,
                 const float* __restrict__ gam, const float* __restrict__ bet,
                 const float* __restrict__ rmean, const float* __restrict__ rvar,
                 float* __restrict__ C, int M, int K, int Nc, int epi)
{
    __shared__ __align__(16) float As[GBK][GBM + 4];
    __shared__ __align__(16) float Bs[GBK][GBN + 4];

    const int tid = threadIdx.x;
    const int tx  = tid & 15;   // 0..15 -> column micro-tile
    const int ty  = tid >> 4;   // 0..15 -> row micro-tile
    const int block_row = blockIdx.y * GBM;
    const int block_col = blockIdx.x * GBN;

    // A tile load mapping: 128x16; 4 threads/row (float4 each), 2 row passes
    const int a_row  = tid >> 2;        // 0..63
    const int a_col4 = (tid & 3) << 2;  // 0,4,8,12
    // B tile load mapping: 16x64; 16 threads/row (float4 each), 1 pass
    const int b_row  = tid >> 4;        // 0..15
    const int b_col4 = (tid & 15) << 2; // 0..60

    float acc[GTM][GTN];
#pragma unroll
    for (int i = 0; i < GTM; ++i)
#pragma unroll
        for (int j = 0; j < GTN; ++j) acc[i][j] = 0.0f;

    for (int k0 = 0; k0 < K; k0 += GBK) {
#pragma unroll
        for (int p = 0; p < 2; ++p) {
            const int r = a_row + p * 64;
            const float4 av = *reinterpret_cast<const float4*>(
                &A[(size_t)(block_row + r) * K + k0 + a_col4]);
            As[a_col4 + 0][r] = av.x;
            As[a_col4 + 1][r] = av.y;
            As[a_col4 + 2][r] = av.z;
            As[a_col4 + 3][r] = av.w;
        }
        {
            const float4 bv = *reinterpret_cast<const float4*>(
                &W[(size_t)(k0 + b_row) * Nc + block_col + b_col4]);
            *reinterpret_cast<float4*>(&Bs[b_row][b_col4]) = bv;
        }
        __syncthreads();

#pragma unroll
        for (int kk = 0; kk < GBK; ++kk) {
            const float4 a0 = *reinterpret_cast<const float4*>(&As[kk][ty * GTM]);
            const float4 a1 = *reinterpret_cast<const float4*>(&As[kk][ty * GTM + 4]);
            const float4 b0 = *reinterpret_cast<const float4*>(&Bs[kk][tx * GTN]);
            const float ar[GTM] = {a0.x, a0.y, a0.z, a0.w, a1.x, a1.y, a1.z, a1.w};
            const float br_[GTN] = {b0.x, b0.y, b0.z, b0.w};
#pragma unroll
            for (int i = 0; i < GTM; ++i)
#pragma unroll
                for (int j = 0; j < GTN; ++j)
                    acc[i][j] = fmaf(ar[i], br_[j], acc[i][j]);
        }
        __syncthreads();
    }

    const int col0 = block_col + tx * GTN;
#pragma unroll
    for (int i = 0; i < GTM; ++i) {
        const int row = block_row + ty * GTM + i;
        float4 o;
        float* ov = &o.x;
#pragma unroll
        for (int j = 0; j < GTN; ++j) {
            const int col = col0 + j;
            float val = acc[i][j] + bias[col];
            if (epi == 1) {
                val = (val - rmean[col]) * rsqrtf(rvar[col] + EPS_BN) * gam[col] + bet[col];
                val = gelu_f(val);
            }
            ov[j] = val;
        }
        *reinterpret_cast<float4*>(&C[(size_t)row * Nc + col0]) = o;
    }
}

// ---------------------------------------------------------------------------
// GATv2 attention + aggregation + bias + GELU (gather, online softmax)
// grid = B*N blocks, block = 128 threads (warp h = head h, 2 channels/lane)
// out[b,n,:] = gelu( segsum_softmax + bo )
// ---------------------------------------------------------------------------
__global__ __launch_bounds__(128)
void gat_attn_kernel(const float* __restrict__ xl, const float* __restrict__ xr,
                     const float* __restrict__ att, const float* __restrict__ bo,
                     float* __restrict__ out)
{
    const int bn   = blockIdx.x;           // b*N + n
    const int n    = bn & (NNODE - 1);
    const int bb   = bn - n;               // b*N
    const int h    = threadIdx.x >> 5;
    const int lane = threadIdx.x & 31;
    const int base = bn * HID + h * CCH + 2 * lane;

    const float2 xi = *reinterpret_cast<const float2*>(&xr[base]);
    const float2 at = *reinterpret_cast<const float2*>(&att[h * CCH + 2 * lane]);

    const int e0 = g_row_ptr[n];
    const int e1 = g_row_ptr[n + 1];

    float m = -INFINITY, den = 0.0f;
    float2 acc = make_float2(0.0f, 0.0f);

    // software-pipelined gather
    float2 xj_next = make_float2(0.0f, 0.0f);
    if (e0 < e1) {
        const int s = g_col_src[e0];
        xj_next = *reinterpret_cast<const float2*>(&xl[(bb + s) * HID + h * CCH + 2 * lane]);
    }

    for (int e = e0; e < e1; ++e) {
        const float2 xj = xj_next;
        if (e + 1 < e1) {
            const int s = g_col_src[e + 1];
            xj_next = *reinterpret_cast<const float2*>(&xl[(bb + s) * HID + h * CCH + 2 * lane]);
        }
        float ex = xi.x + xj.x; ex = (ex > 0.0f) ? ex : NEG_SLOPE * ex;
        float ey = xi.y + xj.y; ey = (ey > 0.0f) ? ey : NEG_SLOPE * ey;
        float p = fmaf(ex, at.x, ey * at.y);
        p += __shfl_xor_sync(0xffffffffu, p, 16);
        p += __shfl_xor_sync(0xffffffffu, p, 8);
        p += __shfl_xor_sync(0xffffffffu, p, 4);
        p += __shfl_xor_sync(0xffffffffu, p, 2);
        p += __shfl_xor_sync(0xffffffffu, p, 1);

        const float mn   = fmaxf(m, p);
        const float corr = __expf(m - mn);   // exp(-inf)=0 handles first edge
        const float w    = __expf(p - mn);
        acc.x = fmaf(acc.x, corr, w * xj.x);
        acc.y = fmaf(acc.y, corr, w * xj.y);
        den   = fmaf(den,  corr, w);
        m = mn;
    }

    const float inv = 1.0f / (den + 1e-16f);
    const float2 b2 = *reinterpret_cast<const float2*>(&bo[h * CCH + 2 * lane]);
    float2 o;
    o.x = gelu_f(fmaf(acc.x, inv, b2.x));
    o.y = gelu_f(fmaf(acc.y, inv, b2.y));
    *reinterpret_cast<float2*>(&out[base]) = o;
}

// ---------------------------------------------------------------------------
// Fused mean-pool over nodes + output_proj + BN + GELU.
// grid = B blocks, block = HID threads.
// ---------------------------------------------------------------------------
__global__ __launch_bounds__(HID)
void pool_proj_kernel(const float* __restrict__ h1, const float* __restrict__ W2,
                      const float* __restrict__ b2, const float* __restrict__ g2,
                      const float* __restrict__ be2, const float* __restrict__ m2,
                      const float* __restrict__ v2, float* __restrict__ out)
{
    const int b = blockIdx.x;
    const int j = threadIdx.x;
    __shared__ float pooled[HID];

    float s = 0.0f;
    const float* hp = h1 + (size_t)b * NNODE * HID + j;
#pragma unroll 4
    for (int n = 0; n < NNODE; ++n) s += hp[(size_t)n * HID];
    pooled[j] = s * (1.0f / (float)NNODE);
    __syncthreads();

    float acc = 0.0f;
#pragma unroll 8
    for (int k = 0; k < HID; ++k)
        acc = fmaf(pooled[k], W2[(size_t)k * HID + j], acc);

    float val = acc + b2[j];
    val = (val - m2[j]) * rsqrtf(v2[j] + EPS_BN) * g2[j] + be2[j];
    out[(size_t)b * HID + j] = gelu_f(val);
}

// ---------------------------------------------------------------------------
// kernel_launch
// Input order (metadata): x, edge_index, W1,b1,g1,be1,m1,v1,
//   Wl0,bl0,Wr0,br0,att0,bo0, Wl1,bl1,Wr1,br1,att1,bo1,
//   W2,b2,g2,be2,m2,v2
// ---------------------------------------------------------------------------
extern "C" void kernel_launch(void* const* d_in, const int* in_sizes, int n_in,
                              void* d_out, int out_size)
{
    const float* x   = (const float*)d_in[0];
    const int*   ei  = (const int*)  d_in[1];
    const float* W1  = (const float*)d_in[2];
    const float* b1  = (const float*)d_in[3];
    const float* g1  = (const float*)d_in[4];
    const float* be1 = (const float*)d_in[5];
    const float* m1  = (const float*)d_in[6];
    const float* v1  = (const float*)d_in[7];
    const float* Wl0 = (const float*)d_in[8];
    const float* bl0 = (const float*)d_in[9];
    const float* Wr0 = (const float*)d_in[10];
    const float* br0 = (const float*)d_in[11];
    const float* at0 = (const float*)d_in[12];
    const float* bo0 = (const float*)d_in[13];
    const float* Wl1 = (const float*)d_in[14];
    const float* bl1 = (const float*)d_in[15];
    const float* Wr1 = (const float*)d_in[16];
    const float* br1 = (const float*)d_in[17];
    const float* at1 = (const float*)d_in[18];
    const float* bo1 = (const float*)d_in[19];
    const float* W2  = (const float*)d_in[20];
    const float* b2  = (const float*)d_in[21];
    const float* g2  = (const float*)d_in[22];
    const float* be2 = (const float*)d_in[23];
    const float* m2  = (const float*)d_in[24];
    const float* v2  = (const float*)d_in[25];
    float* out = (float*)d_out;

    float *p_h, *p_xl, *p_xr, *p_hA, *p_hB;
    cudaGetSymbolAddress((void**)&p_h,  g_h);
    cudaGetSymbolAddress((void**)&p_xl, g_xl);
    cudaGetSymbolAddress((void**)&p_xr, g_xr);
    cudaGetSymbolAddress((void**)&p_hA, g_hA);
    cudaGetSymbolAddress((void**)&p_hB, g_hB);

    const dim3 gblk(256);
    const dim3 ggrid_big(HID / GBN, MROWS / GBM);   // (4, 128)

    // 1) CSR over dst (deterministic)
    build_csr_kernel<<<1, NNODE>>>(ei);

    // 2) node_proj: h = gelu(BN(x @ W1 + b1))
    gemm_kernel<<<ggrid_big, gblk>>>(x, W1, b1, g1, be1, m1, v1,
                                     p_h, MROWS, FIN, HID, 1);

    // 3) layer 0 linear: xl = h@Wl0+bl0 ; xr = h@Wr0+br0
    gemm_kernel<<<ggrid_big, gblk>>>(p_h, Wl0, bl0, 0, 0, 0, 0,
                                     p_xl, MROWS, HID, HID, 0);
    gemm_kernel<<<ggrid_big, gblk>>>(p_h, Wr0, br0, 0, 0, 0, 0,
                                     p_xr, MROWS, HID, HID, 0);

    // 4) layer 0 attention -> hA = gelu(gat + bo0)
    gat_attn_kernel<<<MROWS, 128>>>(p_xl, p_xr, at0, bo0, p_hA);

    // 5) layer 1 linear
    gemm_kernel<<<ggrid_big, gblk>>>(p_hA, Wl1, bl1, 0, 0, 0, 0,
                                     p_xl, MROWS, HID, HID, 0);
    gemm_kernel<<<ggrid_big, gblk>>>(p_hA, Wr1, br1, 0, 0, 0, 0,
                                     p_xr, MROWS, HID, HID, 0);

    // 6) layer 1 attention -> hB
    gat_attn_kernel<<<MROWS, 128>>>(p_xl, p_xr, at1, bo1, p_hB);

    // 7) mean-pool + output_proj + BN + GELU
    pool_proj_kernel<<<BATCH, HID>>>(p_hB, W2, b2, g2, be2, m2, v2, out);
}